// round 4
// baseline (speedup 1.0000x reference)
#include <cuda_runtime.h>
#include <cuda_bf16.h>
#include <math.h>

#define N_NODES   65536
#define N_EDGES   1048576
#define IN_DIM    192
#define PE_DIM    64
#define HIDDEN    256
#define LATENT    128
#define NUM_G     64
#define N_PER     1024
#define K_PER     512
#define N_OUT     (NUM_G * K_PER)          // 32768
#define MAX_DEG   128

// ---------------- scratch (device globals; no allocation allowed) -----------
__device__ float g_buf0[N_NODES * 256];    // pre-agg GEMM out
__device__ float g_buf1[N_NODES * 256];    // h, then [mu|logvar]
__device__ float g_z[N_NODES * LATENT];
__device__ float g_score[N_NODES];
__device__ float g_dinv[N_NODES];
__device__ int   g_cnt[N_NODES];
__device__ int   g_fill[N_NODES];
__device__ int   g_rowstart[N_NODES + 1];
__device__ int   g_colsrc[N_EDGES];
__device__ int   g_coledge[N_EDGES];
__device__ int   g_perm[N_OUT];
__device__ int   g_is64;

// ---------------- edge dtype detection ---------------------------------------
__global__ void k_detect(const void* __restrict__ ei) {
    if (threadIdx.x == 0 && blockIdx.x == 0) {
        const unsigned long long* p = (const unsigned long long*)ei;
        int is64 = 1;
        for (int i = 0; i < 64; i++)
            if (p[i] > 65535ull) { is64 = 0; break; }
        g_is64 = is64;
    }
}

__device__ __forceinline__ int edge_at(const void* __restrict__ ei, int pos) {
    if (g_is64) return (int)((const long long*)ei)[pos];
    return ((const int*)ei)[pos];
}

// ---------------- CSR build ---------------------------------------------------
__global__ void k_zero() {
    int i = blockIdx.x * blockDim.x + threadIdx.x;
    if (i < N_NODES) { g_cnt[i] = 0; g_fill[i] = 0; }
}

__global__ void k_hist(const void* __restrict__ ei) {
    int e = blockIdx.x * blockDim.x + threadIdx.x;
    if (e < N_EDGES) atomicAdd(&g_cnt[edge_at(ei, N_EDGES + e)], 1);
}

__global__ void k_dinv() {
    int i = blockIdx.x * blockDim.x + threadIdx.x;
    if (i < N_NODES)
        g_dinv[i] = (float)(1.0 / sqrt((double)(g_cnt[i] + 1)));  // +1 self loop
}

__global__ void k_scan() {
    __shared__ int sh[1024];
    int t = threadIdx.x;
    int base = t * 64;
    int s = 0;
    for (int j = 0; j < 64; j++) s += g_cnt[base + j];
    sh[t] = s;
    __syncthreads();
    int mine = s;
    for (int off = 1; off < 1024; off <<= 1) {
        int v = (t >= off) ? sh[t - off] : 0;
        __syncthreads();
        sh[t] += v;
        __syncthreads();
    }
    int run = sh[t] - mine;
    for (int j = 0; j < 64; j++) {
        g_rowstart[base + j] = run;
        run += g_cnt[base + j];
    }
    if (t == 1023) g_rowstart[N_NODES] = sh[1023];
}

__global__ void k_scatter(const void* __restrict__ ei) {
    int e = blockIdx.x * blockDim.x + threadIdx.x;
    if (e < N_EDGES) {
        int s = edge_at(ei, e);
        int d = edge_at(ei, N_EDGES + e);
        int pos = g_rowstart[d] + atomicAdd(&g_fill[d], 1);
        g_colsrc[pos] = s;
        g_coledge[pos] = e;
    }
}

// sort each CSR row ascending by edge id -> deterministic accumulation order
__global__ __launch_bounds__(256) void k_sortrows() {
    __shared__ int Es[8][MAX_DEG];
    __shared__ int Ss[8][MAX_DEG];
    int warp = (blockIdx.x * blockDim.x + threadIdx.x) >> 5;
    if (warp >= N_NODES) return;
    int lane = threadIdx.x & 31;
    int w = (threadIdx.x >> 5);
    int e0 = g_rowstart[warp], e1 = g_rowstart[warp + 1];
    int deg = e1 - e0;
    if (deg <= 1) return;
    if (deg > MAX_DEG) deg = MAX_DEG;
    for (int i = lane; i < deg; i += 32) {
        Es[w][i] = g_coledge[e0 + i];
        Ss[w][i] = g_colsrc[e0 + i];
    }
    __syncwarp();
    for (int i = lane; i < deg; i += 32) {
        int my_e = Es[w][i];
        int rank = 0;
        for (int j = 0; j < deg; j++) rank += (Es[w][j] < my_e);
        g_colsrc[e0 + rank] = Ss[w][i];
    }
}

// ---------------- GEMM: C[65536x256] = A[65536x256] @ B[256x256] -------------
template <int MODE>
__global__ __launch_bounds__(256) void k_gemm(
    const float* __restrict__ A0, const float* __restrict__ A1,
    const float* __restrict__ B0, const float* __restrict__ B1,
    float* __restrict__ C)
{
    __shared__ float As[16][65];
    __shared__ float Bs[16][64];
    int tid = threadIdx.x;
    int tx = tid & 15, ty = tid >> 4;
    int m0 = blockIdx.x * 64;
    int n0 = blockIdx.y * 64;
    float acc[4][4] = {};

    for (int k0 = 0; k0 < 256; k0 += 16) {
        #pragma unroll
        for (int i = 0; i < 4; i++) {
            int idx = tid + i * 256;
            int m = idx >> 4, k = idx & 15;
            int row = m0 + m, col = k0 + k;
            float v;
            if (MODE == 0)
                v = (col < IN_DIM) ? A0[row * IN_DIM + col]
                                   : A1[row * PE_DIM + (col - IN_DIM)];
            else
                v = A0[row * 256 + col];
            As[k][m] = v;
        }
        #pragma unroll
        for (int i = 0; i < 4; i++) {
            int idx = tid + i * 256;
            int k = idx >> 6, n = idx & 63;
            int col = n0 + n;
            float v;
            if (MODE == 0)
                v = B0[(k0 + k) * 256 + col];
            else
                v = (col < 128) ? B0[(k0 + k) * 128 + col]
                                : B1[(k0 + k) * 128 + (col - 128)];
            Bs[k][n] = v;
        }
        __syncthreads();
        float accT[4][4] = {};   // per-tile partial (lower accumulation error)
        #pragma unroll
        for (int k = 0; k < 16; k++) {
            float a[4], b[4];
            #pragma unroll
            for (int i = 0; i < 4; i++) a[i] = As[k][ty * 4 + i];
            #pragma unroll
            for (int j = 0; j < 4; j++) b[j] = Bs[k][tx * 4 + j];
            #pragma unroll
            for (int i = 0; i < 4; i++)
                #pragma unroll
                for (int j = 0; j < 4; j++)
                    accT[i][j] = fmaf(a[i], b[j], accT[i][j]);
        }
        #pragma unroll
        for (int i = 0; i < 4; i++)
            #pragma unroll
            for (int j = 0; j < 4; j++)
                acc[i][j] = __fadd_rn(acc[i][j], accT[i][j]);
        __syncthreads();
    }
    #pragma unroll
    for (int i = 0; i < 4; i++) {
        float4 o = make_float4(acc[i][0], acc[i][1], acc[i][2], acc[i][3]);
        *(float4*)&C[(m0 + ty * 4 + i) * 256 + n0 + tx * 4] = o;
    }
}

// ---------------- normalized aggregation, reference accumulation order -------
// acc = sum_{edges asc e} norm_e*in[src]  ; then += nself*in[d] ; then += bias
__global__ __launch_bounds__(256) void k_agg(
    const float* __restrict__ in, float* __restrict__ out,
    const float* __restrict__ bias0, const float* __restrict__ bias1, int relu)
{
    int warp = (blockIdx.x * blockDim.x + threadIdx.x) >> 5;
    if (warp >= N_NODES) return;
    int lane = threadIdx.x & 31;
    int d = warp;
    float dd = g_dinv[d];
    const float4* in4 = (const float4*)in;

    float a0[4] = {0.f, 0.f, 0.f, 0.f};
    float a1[4] = {0.f, 0.f, 0.f, 0.f};

    int e0 = g_rowstart[d], e1 = g_rowstart[d + 1];
    for (int e = e0; e < e1; e++) {
        int s = g_colsrc[e];
        float nrm = __fmul_rn(g_dinv[s], dd);
        float4 b0 = in4[s * 64 + lane];
        float4 b1 = in4[s * 64 + 32 + lane];
        a0[0] = __fadd_rn(a0[0], __fmul_rn(nrm, b0.x));
        a0[1] = __fadd_rn(a0[1], __fmul_rn(nrm, b0.y));
        a0[2] = __fadd_rn(a0[2], __fmul_rn(nrm, b0.z));
        a0[3] = __fadd_rn(a0[3], __fmul_rn(nrm, b0.w));
        a1[0] = __fadd_rn(a1[0], __fmul_rn(nrm, b1.x));
        a1[1] = __fadd_rn(a1[1], __fmul_rn(nrm, b1.y));
        a1[2] = __fadd_rn(a1[2], __fmul_rn(nrm, b1.z));
        a1[3] = __fadd_rn(a1[3], __fmul_rn(nrm, b1.w));
    }
    // self loop (appended last in reference edge list)
    {
        float nself = __fmul_rn(dd, dd);
        float4 b0 = in4[d * 64 + lane];
        float4 b1 = in4[d * 64 + 32 + lane];
        a0[0] = __fadd_rn(a0[0], __fmul_rn(nself, b0.x));
        a0[1] = __fadd_rn(a0[1], __fmul_rn(nself, b0.y));
        a0[2] = __fadd_rn(a0[2], __fmul_rn(nself, b0.z));
        a0[3] = __fadd_rn(a0[3], __fmul_rn(nself, b0.w));
        a1[0] = __fadd_rn(a1[0], __fmul_rn(nself, b1.x));
        a1[1] = __fadd_rn(a1[1], __fmul_rn(nself, b1.y));
        a1[2] = __fadd_rn(a1[2], __fmul_rn(nself, b1.z));
        a1[3] = __fadd_rn(a1[3], __fmul_rn(nself, b1.w));
    }
    int c = lane * 4;
    #pragma unroll
    for (int j = 0; j < 4; j++) {
        a0[j] = __fadd_rn(a0[j], bias0[c + j]);
        a1[j] = __fadd_rn(a1[j], bias1[c + j]);
        if (relu) { a0[j] = fmaxf(a0[j], 0.f); a1[j] = fmaxf(a1[j], 0.f); }
    }
    float4* out4 = (float4*)out;
    out4[d * 64 + lane]      = make_float4(a0[0], a0[1], a0[2], a0[3]);
    out4[d * 64 + 32 + lane] = make_float4(a1[0], a1[1], a1[2], a1[3]);
}

// ---------------- z = mu + eps*exp(0.5*lv); score via double dot -------------
__global__ __launch_bounds__(256) void k_zscore(
    const float* __restrict__ eps, const float* __restrict__ w)
{
    int warp = (blockIdx.x * blockDim.x + threadIdx.x) >> 5;
    if (warp >= N_NODES) return;
    int lane = threadIdx.x & 31;
    int n = warp;
    const float4* muv4 = (const float4*)g_buf1;
    float4 mu = muv4[n * 64 + lane];
    float4 lv = muv4[n * 64 + 32 + lane];
    float4 ep = ((const float4*)eps)[n * 32 + lane];
    float4 wv = ((const float4*)w)[lane];
    float4 z;
    z.x = __fadd_rn(mu.x, __fmul_rn(ep.x, (float)exp(0.5 * (double)lv.x)));
    z.y = __fadd_rn(mu.y, __fmul_rn(ep.y, (float)exp(0.5 * (double)lv.y)));
    z.z = __fadd_rn(mu.z, __fmul_rn(ep.z, (float)exp(0.5 * (double)lv.z)));
    z.w = __fadd_rn(mu.w, __fmul_rn(ep.w, (float)exp(0.5 * (double)lv.w)));
    double dot = (double)z.x * wv.x + (double)z.y * wv.y
               + (double)z.z * wv.z + (double)z.w * wv.w;
    double wsq = (double)wv.x * wv.x + (double)wv.y * wv.y
               + (double)wv.z * wv.z + (double)wv.w * wv.w;
    #pragma unroll
    for (int o = 16; o > 0; o >>= 1) {
        dot += __shfl_xor_sync(0xffffffffu, dot, o);
        wsq += __shfl_xor_sync(0xffffffffu, wsq, o);
    }
    ((float4*)g_z)[n * 32 + lane] = z;
    if (lane == 0) g_score[n] = (float)tanh(dot / sqrt(wsq));
}

// ---------------- per-graph top-k: bitonic sort of 1024 ----------------------
__device__ __forceinline__ bool later_than(float sa, int ia, float sb, int ib) {
    return (sa < sb) || (sa == sb && ia > ib);
}

__global__ __launch_bounds__(512) void k_topk() {
    __shared__ float ss[1024];
    __shared__ int   si[1024];
    int g = blockIdx.x;
    int t = threadIdx.x;
    int base = g * N_PER;
    ss[t] = g_score[base + t];             si[t] = t;
    ss[t + 512] = g_score[base + t + 512]; si[t + 512] = t + 512;
    __syncthreads();
    for (int k = 2; k <= 1024; k <<= 1) {
        for (int j = k >> 1; j > 0; j >>= 1) {
            for (int i = t; i < 1024; i += 512) {
                int l = i ^ j;
                if (l > i) {
                    bool up = ((i & k) == 0);
                    if (later_than(ss[i], si[i], ss[l], si[l]) == up) {
                        float ts = ss[i]; ss[i] = ss[l]; ss[l] = ts;
                        int ti = si[i]; si[i] = si[l]; si[l] = ti;
                    }
                }
            }
            __syncthreads();
        }
    }
    g_perm[g * K_PER + t] = base + si[t];
}

// ---------------- gather epilogue --------------------------------------------
__global__ __launch_bounds__(256) void k_output(float* __restrict__ out) {
    const int OFF_MU = N_OUT * LATENT;
    const int OFF_LV = 2 * N_OUT * LATENT;
    const int OFF_B  = 3 * N_OUT * LATENT;
    const int OFF_P  = OFF_B + N_OUT;
    int warp = (blockIdx.x * blockDim.x + threadIdx.x) >> 5;
    if (warp >= N_OUT) return;
    int lane = threadIdx.x & 31;
    int node = g_perm[warp];
    float sc = g_score[node];
    float4 z = ((const float4*)g_z)[node * 32 + lane];
    z.x = __fmul_rn(z.x, sc); z.y = __fmul_rn(z.y, sc);
    z.z = __fmul_rn(z.z, sc); z.w = __fmul_rn(z.w, sc);
    ((float4*)out)[warp * 32 + lane] = z;
    const float4* muv4 = (const float4*)g_buf1;
    ((float4*)(out + OFF_MU))[warp * 32 + lane] = muv4[node * 64 + lane];
    ((float4*)(out + OFF_LV))[warp * 32 + lane] = muv4[node * 64 + 32 + lane];
    if (lane == 0) {
        out[OFF_B + warp] = (float)(node >> 10);
        out[OFF_P + warp] = (float)node;
    }
}

// ---------------- launch ------------------------------------------------------
extern "C" void kernel_launch(void* const* d_in, const int* in_sizes, int n_in,
                              void* d_out, int out_size)
{
    const float* x_raw = (const float*)d_in[0];
    const float* pe    = (const float*)d_in[1];
    const void*  ei    = d_in[2];
    const float* eps   = (const float*)d_in[4];
    const float* W1    = (const float*)d_in[5];
    const float* b1    = (const float*)d_in[6];
    const float* Wmu   = (const float*)d_in[7];
    const float* bmu   = (const float*)d_in[8];
    const float* Wlv   = (const float*)d_in[9];
    const float* blv   = (const float*)d_in[10];
    const float* wpool = (const float*)d_in[11];
    float* out = (float*)d_out;

    float* buf0; cudaGetSymbolAddress((void**)&buf0, g_buf0);
    float* buf1; cudaGetSymbolAddress((void**)&buf1, g_buf1);

    k_detect<<<1, 32>>>(ei);
    k_zero<<<N_NODES / 256, 256>>>();
    k_hist<<<N_EDGES / 256, 256>>>(ei);
    k_dinv<<<N_NODES / 256, 256>>>();
    k_scan<<<1, 1024>>>();
    k_scatter<<<N_EDGES / 256, 256>>>(ei);
    k_sortrows<<<(N_NODES * 32) / 256, 256>>>();

    dim3 gg(N_NODES / 64, 256 / 64);
    k_gemm<0><<<gg, 256>>>(x_raw, pe, W1, nullptr, buf0);
    k_agg<<<(N_NODES * 32) / 256, 256>>>(buf0, buf1, b1, b1 + 128, 1);
    k_gemm<1><<<gg, 256>>>(buf1, nullptr, Wmu, Wlv, buf0);
    k_agg<<<(N_NODES * 32) / 256, 256>>>(buf0, buf1, bmu, blv, 0);

    k_zscore<<<(N_NODES * 32) / 256, 256>>>(eps, wpool);
    k_topk<<<NUM_G, 512>>>();
    k_output<<<(N_OUT * 32) / 256, 256>>>(out);
}

// round 5
// speedup vs baseline: 1.3545x; 1.3545x over previous
#include <cuda_runtime.h>
#include <cuda_bf16.h>
#include <math.h>

#define N_NODES   65536
#define N_EDGES   1048576
#define IN_DIM    192
#define PE_DIM    64
#define HIDDEN    256
#define LATENT    128
#define NUM_G     64
#define N_PER     1024
#define K_PER     512
#define N_OUT     (NUM_G * K_PER)          // 32768
#define MAX_DEG   128

typedef unsigned long long u64;

// ---------------- packed f32x2 helpers (sm_103a FFMA2 pipe) ------------------
__device__ __forceinline__ u64 ffma2(u64 a, u64 b, u64 c) {
    u64 d;
    asm("fma.rn.f32x2 %0, %1, %2, %3;" : "=l"(d) : "l"(a), "l"(b), "l"(c));
    return d;
}
__device__ __forceinline__ u64 fadd2(u64 a, u64 b) {
    u64 d;
    asm("add.rn.f32x2 %0, %1, %2;" : "=l"(d) : "l"(a), "l"(b));
    return d;
}
__device__ __forceinline__ u64 pack2(float lo, float hi) {
    u64 d;
    asm("mov.b64 %0, {%1, %2};" : "=l"(d) : "f"(lo), "f"(hi));
    return d;
}
__device__ __forceinline__ void unpack2(u64 v, float& lo, float& hi) {
    asm("mov.b64 {%0, %1}, %2;" : "=f"(lo), "=f"(hi) : "l"(v));
}

// ---------------- scratch (device globals; no allocation allowed) -----------
__device__ float g_buf0[N_NODES * 256];
__device__ float g_buf1[N_NODES * 256];
__device__ float g_z[N_NODES * LATENT];
__device__ float g_score[N_NODES];
__device__ float g_dinv[N_NODES];
__device__ int   g_cnt[N_NODES];
__device__ int   g_fill[N_NODES];
__device__ int   g_rowstart[N_NODES + 1];
__device__ int   g_colsrc[N_EDGES];
__device__ int   g_coledge[N_EDGES];
__device__ int   g_perm[N_OUT];
__device__ int   g_is64;

// ---------------- edge dtype detection ---------------------------------------
__global__ void k_detect(const void* __restrict__ ei) {
    if (threadIdx.x == 0 && blockIdx.x == 0) {
        const unsigned long long* p = (const unsigned long long*)ei;
        int is64 = 1;
        for (int i = 0; i < 64; i++)
            if (p[i] > 65535ull) { is64 = 0; break; }
        g_is64 = is64;
    }
}

__device__ __forceinline__ int edge_at(const void* __restrict__ ei, int pos) {
    if (g_is64) return (int)((const long long*)ei)[pos];
    return ((const int*)ei)[pos];
}

// ---------------- CSR build ---------------------------------------------------
__global__ void k_zero() {
    int i = blockIdx.x * blockDim.x + threadIdx.x;
    if (i < N_NODES) { g_cnt[i] = 0; g_fill[i] = 0; }
}

__global__ void k_hist(const void* __restrict__ ei) {
    int e = blockIdx.x * blockDim.x + threadIdx.x;
    if (e < N_EDGES) atomicAdd(&g_cnt[edge_at(ei, N_EDGES + e)], 1);
}

__global__ void k_dinv() {
    int i = blockIdx.x * blockDim.x + threadIdx.x;
    if (i < N_NODES)
        g_dinv[i] = (float)(1.0 / sqrt((double)(g_cnt[i] + 1)));
}

__global__ void k_scan() {
    __shared__ int sh[1024];
    int t = threadIdx.x;
    int base = t * 64;
    int s = 0;
    for (int j = 0; j < 64; j++) s += g_cnt[base + j];
    sh[t] = s;
    __syncthreads();
    int mine = s;
    for (int off = 1; off < 1024; off <<= 1) {
        int v = (t >= off) ? sh[t - off] : 0;
        __syncthreads();
        sh[t] += v;
        __syncthreads();
    }
    int run = sh[t] - mine;
    for (int j = 0; j < 64; j++) {
        g_rowstart[base + j] = run;
        run += g_cnt[base + j];
    }
    if (t == 1023) g_rowstart[N_NODES] = sh[1023];
}

__global__ void k_scatter(const void* __restrict__ ei) {
    int e = blockIdx.x * blockDim.x + threadIdx.x;
    if (e < N_EDGES) {
        int s = edge_at(ei, e);
        int d = edge_at(ei, N_EDGES + e);
        int pos = g_rowstart[d] + atomicAdd(&g_fill[d], 1);
        g_colsrc[pos] = s;
        g_coledge[pos] = e;
    }
}

__global__ __launch_bounds__(256) void k_sortrows() {
    __shared__ int Es[8][MAX_DEG];
    __shared__ int Ss[8][MAX_DEG];
    int warp = (blockIdx.x * blockDim.x + threadIdx.x) >> 5;
    if (warp >= N_NODES) return;
    int lane = threadIdx.x & 31;
    int w = (threadIdx.x >> 5);
    int e0 = g_rowstart[warp], e1 = g_rowstart[warp + 1];
    int deg = e1 - e0;
    if (deg <= 1) return;
    if (deg > MAX_DEG) deg = MAX_DEG;
    for (int i = lane; i < deg; i += 32) {
        Es[w][i] = g_coledge[e0 + i];
        Ss[w][i] = g_colsrc[e0 + i];
    }
    __syncwarp();
    for (int i = lane; i < deg; i += 32) {
        int my_e = Es[w][i];
        int rank = 0;
        for (int j = 0; j < deg; j++) rank += (Es[w][j] < my_e);
        g_colsrc[e0 + rank] = Ss[w][i];
    }
}

// ---------------- GEMM (f32x2 packed): C[65536x256] = A @ B ------------------
// Block tile 128x64, 256 threads, per-thread 8 rows (4 M-pairs) x 4 cols.
// Accumulation per element: 16-deep k-tile partial (IEEE FMA chain) then
// round-to-nearest add into running sum — bitwise identical to round-4 kernel.
template <int MODE>
__global__ __launch_bounds__(256) void k_gemm(
    const float* __restrict__ A0, const float* __restrict__ A1,
    const float* __restrict__ B0, const float* __restrict__ B1,
    float* __restrict__ C)
{
    __shared__ float As[16][130];   // [k][m], pad 130 -> conflict-free stores
    __shared__ float Bs[16][64];    // [k][n]
    int tid = threadIdx.x;
    int tx = tid & 15, ty = tid >> 4;
    int m0 = blockIdx.x * 128;
    int n0 = blockIdx.y * 64;

    u64 acc[4][4];
    #pragma unroll
    for (int i = 0; i < 4; i++)
        #pragma unroll
        for (int j = 0; j < 4; j++) acc[i][j] = 0ull;

    for (int k0 = 0; k0 < 256; k0 += 16) {
        // A tile: 128 rows x 16 k  (512 float4, 2 per thread), transpose to As[k][m]
        #pragma unroll
        for (int i = 0; i < 2; i++) {
            int idx = tid + i * 256;
            int row = idx >> 2;
            int q   = (idx & 3) * 4;
            int col = k0 + q;
            float4 v;
            if (MODE == 0) {
                if (col < IN_DIM)
                    v = *(const float4*)&A0[(m0 + row) * IN_DIM + col];
                else
                    v = *(const float4*)&A1[(m0 + row) * PE_DIM + (col - IN_DIM)];
            } else {
                v = *(const float4*)&A0[(m0 + row) * 256 + col];
            }
            As[q + 0][row] = v.x; As[q + 1][row] = v.y;
            As[q + 2][row] = v.z; As[q + 3][row] = v.w;
        }
        // B tile: 16 k x 64 n (256 float4, 1 per thread)
        {
            int row = tid >> 4;
            int q   = (tid & 15) * 4;
            int col = n0 + q;
            float4 v;
            if (MODE == 0)
                v = *(const float4*)&B0[(k0 + row) * 256 + col];
            else
                v = (col < 128) ? *(const float4*)&B0[(k0 + row) * 128 + col]
                                : *(const float4*)&B1[(k0 + row) * 128 + (col - 128)];
            *(float4*)&Bs[row][q] = v;
        }
        __syncthreads();

        u64 accT[4][4];
        #pragma unroll
        for (int i = 0; i < 4; i++)
            #pragma unroll
            for (int j = 0; j < 4; j++) accT[i][j] = 0ull;

        #pragma unroll
        for (int k = 0; k < 16; k++) {
            u64 ap[4];
            #pragma unroll
            for (int i = 0; i < 4; i++)
                ap[i] = *(const u64*)&As[k][ty * 8 + 2 * i];
            float4 bv = *(const float4*)&Bs[k][tx * 4];
            u64 bp[4] = { pack2(bv.x, bv.x), pack2(bv.y, bv.y),
                          pack2(bv.z, bv.z), pack2(bv.w, bv.w) };
            #pragma unroll
            for (int i = 0; i < 4; i++)
                #pragma unroll
                for (int j = 0; j < 4; j++)
                    accT[i][j] = ffma2(ap[i], bp[j], accT[i][j]);
        }
        #pragma unroll
        for (int i = 0; i < 4; i++)
            #pragma unroll
            for (int j = 0; j < 4; j++)
                acc[i][j] = fadd2(acc[i][j], accT[i][j]);
        __syncthreads();
    }
    #pragma unroll
    for (int i = 0; i < 4; i++) {
        float lo[4], hi[4];
        #pragma unroll
        for (int j = 0; j < 4; j++) unpack2(acc[i][j], lo[j], hi[j]);
        int r0 = m0 + ty * 8 + 2 * i;
        *(float4*)&C[r0 * 256 + n0 + tx * 4]       = make_float4(lo[0], lo[1], lo[2], lo[3]);
        *(float4*)&C[(r0 + 1) * 256 + n0 + tx * 4] = make_float4(hi[0], hi[1], hi[2], hi[3]);
    }
}

// ---------------- normalized aggregation: 2 warps per node (halves) ---------
__global__ __launch_bounds__(256) void k_agg(
    const float* __restrict__ in, float* __restrict__ out,
    const float* __restrict__ bias0, const float* __restrict__ bias1, int relu)
{
    int gw = (blockIdx.x * blockDim.x + threadIdx.x) >> 5;
    if (gw >= N_NODES * 2) return;
    int lane = threadIdx.x & 31;
    int d = gw >> 1;
    int half = gw & 1;
    const float4* in4 = (const float4*)in + half * 32;
    float dd = g_dinv[d];

    float a0 = 0.f, a1 = 0.f, a2 = 0.f, a3 = 0.f;
    int e0 = g_rowstart[d], e1 = g_rowstart[d + 1];
    int e = e0;
    for (; e + 1 < e1; e += 2) {
        int s0 = g_colsrc[e], s1 = g_colsrc[e + 1];
        float n0 = __fmul_rn(g_dinv[s0], dd);
        float n1 = __fmul_rn(g_dinv[s1], dd);
        float4 b0 = in4[s0 * 64 + lane];
        float4 b1 = in4[s1 * 64 + lane];
        a0 = __fadd_rn(a0, __fmul_rn(n0, b0.x));
        a1 = __fadd_rn(a1, __fmul_rn(n0, b0.y));
        a2 = __fadd_rn(a2, __fmul_rn(n0, b0.z));
        a3 = __fadd_rn(a3, __fmul_rn(n0, b0.w));
        a0 = __fadd_rn(a0, __fmul_rn(n1, b1.x));
        a1 = __fadd_rn(a1, __fmul_rn(n1, b1.y));
        a2 = __fadd_rn(a2, __fmul_rn(n1, b1.z));
        a3 = __fadd_rn(a3, __fmul_rn(n1, b1.w));
    }
    if (e < e1) {
        int s0 = g_colsrc[e];
        float n0 = __fmul_rn(g_dinv[s0], dd);
        float4 b0 = in4[s0 * 64 + lane];
        a0 = __fadd_rn(a0, __fmul_rn(n0, b0.x));
        a1 = __fadd_rn(a1, __fmul_rn(n0, b0.y));
        a2 = __fadd_rn(a2, __fmul_rn(n0, b0.z));
        a3 = __fadd_rn(a3, __fmul_rn(n0, b0.w));
    }
    {   // self loop last, as in reference edge list
        float ns = __fmul_rn(dd, dd);
        float4 b = in4[d * 64 + lane];
        a0 = __fadd_rn(a0, __fmul_rn(ns, b.x));
        a1 = __fadd_rn(a1, __fmul_rn(ns, b.y));
        a2 = __fadd_rn(a2, __fmul_rn(ns, b.z));
        a3 = __fadd_rn(a3, __fmul_rn(ns, b.w));
    }
    const float* bias = half ? bias1 : bias0;
    int c = lane * 4;
    a0 = __fadd_rn(a0, bias[c + 0]);
    a1 = __fadd_rn(a1, bias[c + 1]);
    a2 = __fadd_rn(a2, bias[c + 2]);
    a3 = __fadd_rn(a3, bias[c + 3]);
    if (relu) {
        a0 = fmaxf(a0, 0.f); a1 = fmaxf(a1, 0.f);
        a2 = fmaxf(a2, 0.f); a3 = fmaxf(a3, 0.f);
    }
    ((float4*)out + half * 32)[d * 64 + lane] = make_float4(a0, a1, a2, a3);
}

// ---------------- z = mu + eps*expf(0.5*lv); score via double dot ------------
__global__ __launch_bounds__(256) void k_zscore(
    const float* __restrict__ eps, const float* __restrict__ w)
{
    int warp = (blockIdx.x * blockDim.x + threadIdx.x) >> 5;
    if (warp >= N_NODES) return;
    int lane = threadIdx.x & 31;
    int n = warp;
    const float4* muv4 = (const float4*)g_buf1;
    float4 mu = muv4[n * 64 + lane];
    float4 lv = muv4[n * 64 + 32 + lane];
    float4 ep = ((const float4*)eps)[n * 32 + lane];
    float4 wv = ((const float4*)w)[lane];
    float4 z;
    z.x = __fadd_rn(mu.x, __fmul_rn(ep.x, expf(__fmul_rn(0.5f, lv.x))));
    z.y = __fadd_rn(mu.y, __fmul_rn(ep.y, expf(__fmul_rn(0.5f, lv.y))));
    z.z = __fadd_rn(mu.z, __fmul_rn(ep.z, expf(__fmul_rn(0.5f, lv.z))));
    z.w = __fadd_rn(mu.w, __fmul_rn(ep.w, expf(__fmul_rn(0.5f, lv.w))));
    double dot = (double)z.x * wv.x + (double)z.y * wv.y
               + (double)z.z * wv.z + (double)z.w * wv.w;
    double wsq = (double)wv.x * wv.x + (double)wv.y * wv.y
               + (double)wv.z * wv.z + (double)wv.w * wv.w;
    #pragma unroll
    for (int o = 16; o > 0; o >>= 1) {
        dot += __shfl_xor_sync(0xffffffffu, dot, o);
        wsq += __shfl_xor_sync(0xffffffffu, wsq, o);
    }
    ((float4*)g_z)[n * 32 + lane] = z;
    if (lane == 0) g_score[n] = (float)tanh(dot / sqrt(wsq));
}

// ---------------- per-graph top-k: bitonic sort of 1024 ----------------------
__device__ __forceinline__ bool later_than(float sa, int ia, float sb, int ib) {
    return (sa < sb) || (sa == sb && ia > ib);
}

__global__ __launch_bounds__(512) void k_topk() {
    __shared__ float ss[1024];
    __shared__ int   si[1024];
    int g = blockIdx.x;
    int t = threadIdx.x;
    int base = g * N_PER;
    ss[t] = g_score[base + t];             si[t] = t;
    ss[t + 512] = g_score[base + t + 512]; si[t + 512] = t + 512;
    __syncthreads();
    for (int k = 2; k <= 1024; k <<= 1) {
        for (int j = k >> 1; j > 0; j >>= 1) {
            for (int i = t; i < 1024; i += 512) {
                int l = i ^ j;
                if (l > i) {
                    bool up = ((i & k) == 0);
                    if (later_than(ss[i], si[i], ss[l], si[l]) == up) {
                        float ts = ss[i]; ss[i] = ss[l]; ss[l] = ts;
                        int ti = si[i]; si[i] = si[l]; si[l] = ti;
                    }
                }
            }
            __syncthreads();
        }
    }
    g_perm[g * K_PER + t] = base + si[t];
}

// ---------------- gather epilogue --------------------------------------------
__global__ __launch_bounds__(256) void k_output(float* __restrict__ out) {
    const int OFF_MU = N_OUT * LATENT;
    const int OFF_LV = 2 * N_OUT * LATENT;
    const int OFF_B  = 3 * N_OUT * LATENT;
    const int OFF_P  = OFF_B + N_OUT;
    int warp = (blockIdx.x * blockDim.x + threadIdx.x) >> 5;
    if (warp >= N_OUT) return;
    int lane = threadIdx.x & 31;
    int node = g_perm[warp];
    float sc = g_score[node];
    float4 z = ((const float4*)g_z)[node * 32 + lane];
    z.x = __fmul_rn(z.x, sc); z.y = __fmul_rn(z.y, sc);
    z.z = __fmul_rn(z.z, sc); z.w = __fmul_rn(z.w, sc);
    ((float4*)out)[warp * 32 + lane] = z;
    const float4* muv4 = (const float4*)g_buf1;
    ((float4*)(out + OFF_MU))[warp * 32 + lane] = muv4[node * 64 + lane];
    ((float4*)(out + OFF_LV))[warp * 32 + lane] = muv4[node * 64 + 32 + lane];
    if (lane == 0) {
        out[OFF_B + warp] = (float)(node >> 10);
        out[OFF_P + warp] = (float)node;
    }
}

// ---------------- launch ------------------------------------------------------
extern "C" void kernel_launch(void* const* d_in, const int* in_sizes, int n_in,
                              void* d_out, int out_size)
{
    const float* x_raw = (const float*)d_in[0];
    const float* pe    = (const float*)d_in[1];
    const void*  ei    = d_in[2];
    const float* eps   = (const float*)d_in[4];
    const float* W1    = (const float*)d_in[5];
    const float* b1    = (const float*)d_in[6];
    const float* Wmu   = (const float*)d_in[7];
    const float* bmu   = (const float*)d_in[8];
    const float* Wlv   = (const float*)d_in[9];
    const float* blv   = (const float*)d_in[10];
    const float* wpool = (const float*)d_in[11];
    float* out = (float*)d_out;

    float* buf0; cudaGetSymbolAddress((void**)&buf0, g_buf0);
    float* buf1; cudaGetSymbolAddress((void**)&buf1, g_buf1);

    k_detect<<<1, 32>>>(ei);
    k_zero<<<N_NODES / 256, 256>>>();
    k_hist<<<N_EDGES / 256, 256>>>(ei);
    k_dinv<<<N_NODES / 256, 256>>>();
    k_scan<<<1, 1024>>>();
    k_scatter<<<N_EDGES / 256, 256>>>(ei);
    k_sortrows<<<(N_NODES * 32) / 256, 256>>>();

    dim3 gg(N_NODES / 128, 256 / 64);
    k_gemm<0><<<gg, 256>>>(x_raw, pe, W1, nullptr, buf0);
    k_agg<<<(N_NODES * 64) / 256, 256>>>(buf0, buf1, b1, b1 + 128, 1);
    k_gemm<1><<<gg, 256>>>(buf1, nullptr, Wmu, Wlv, buf0);
    k_agg<<<(N_NODES * 64) / 256, 256>>>(buf0, buf1, bmu, blv, 0);

    k_zscore<<<(N_NODES * 32) / 256, 256>>>(eps, wpool);
    k_topk<<<NUM_G, 512>>>();
    k_output<<<(N_OUT * 32) / 256, 256>>>(out);
}

// round 6
// speedup vs baseline: 1.4251x; 1.0521x over previous
#include <cuda_runtime.h>
#include <cuda_bf16.h>
#include <math.h>

#define N_NODES   65536
#define N_EDGES   1048576
#define IN_DIM    192
#define PE_DIM    64
#define HIDDEN    256
#define LATENT    128
#define NUM_G     64
#define N_PER     1024
#define K_PER     512
#define N_OUT     (NUM_G * K_PER)          // 32768
#define MAX_DEG   128

typedef unsigned long long u64;

// ---------------- packed f32x2 helpers (sm_103a FFMA2 pipe) ------------------
__device__ __forceinline__ u64 ffma2(u64 a, u64 b, u64 c) {
    u64 d;
    asm("fma.rn.f32x2 %0, %1, %2, %3;" : "=l"(d) : "l"(a), "l"(b), "l"(c));
    return d;
}
__device__ __forceinline__ u64 fadd2(u64 a, u64 b) {
    u64 d;
    asm("add.rn.f32x2 %0, %1, %2;" : "=l"(d) : "l"(a), "l"(b));
    return d;
}
__device__ __forceinline__ u64 pack2(float lo, float hi) {
    u64 d;
    asm("mov.b64 %0, {%1, %2};" : "=l"(d) : "f"(lo), "f"(hi));
    return d;
}
__device__ __forceinline__ void unpack2(u64 v, float& lo, float& hi) {
    asm("mov.b64 {%0, %1}, %2;" : "=f"(lo), "=f"(hi) : "l"(v));
}

// ---------------- scratch (device globals; no allocation allowed) -----------
__device__ float g_buf0[N_NODES * 256];
__device__ float g_buf1[N_NODES * 256];
__device__ float g_z[N_NODES * LATENT];
__device__ float g_score[N_NODES];
__device__ float g_dinv[N_NODES];
__device__ int   g_cnt[N_NODES];
__device__ int   g_fill[N_NODES];
__device__ int   g_rowstart[N_NODES + 1];
__device__ int   g_colsrc[N_EDGES];
__device__ int   g_coledge[N_EDGES];
__device__ int   g_perm[N_OUT];
__device__ int   g_is64;

// ---------------- edge dtype detection ---------------------------------------
__global__ void k_detect(const void* __restrict__ ei) {
    if (threadIdx.x == 0 && blockIdx.x == 0) {
        const unsigned long long* p = (const unsigned long long*)ei;
        int is64 = 1;
        for (int i = 0; i < 64; i++)
            if (p[i] > 65535ull) { is64 = 0; break; }
        g_is64 = is64;
    }
}

__device__ __forceinline__ int edge_at(const void* __restrict__ ei, int pos) {
    if (g_is64) return (int)((const long long*)ei)[pos];
    return ((const int*)ei)[pos];
}

// ---------------- CSR build ---------------------------------------------------
__global__ void k_zero() {
    int i = blockIdx.x * blockDim.x + threadIdx.x;
    if (i < N_NODES) { g_cnt[i] = 0; g_fill[i] = 0; }
}

__global__ void k_hist(const void* __restrict__ ei) {
    int e = blockIdx.x * blockDim.x + threadIdx.x;
    if (e < N_EDGES) atomicAdd(&g_cnt[edge_at(ei, N_EDGES + e)], 1);
}

__global__ void k_dinv() {
    int i = blockIdx.x * blockDim.x + threadIdx.x;
    if (i < N_NODES)
        g_dinv[i] = (float)(1.0 / sqrt((double)(g_cnt[i] + 1)));
}

__global__ void k_scan() {
    __shared__ int sh[1024];
    int t = threadIdx.x;
    int base = t * 64;
    int s = 0;
    for (int j = 0; j < 64; j++) s += g_cnt[base + j];
    sh[t] = s;
    __syncthreads();
    int mine = s;
    for (int off = 1; off < 1024; off <<= 1) {
        int v = (t >= off) ? sh[t - off] : 0;
        __syncthreads();
        sh[t] += v;
        __syncthreads();
    }
    int run = sh[t] - mine;
    for (int j = 0; j < 64; j++) {
        g_rowstart[base + j] = run;
        run += g_cnt[base + j];
    }
    if (t == 1023) g_rowstart[N_NODES] = sh[1023];
}

__global__ void k_scatter(const void* __restrict__ ei) {
    int e = blockIdx.x * blockDim.x + threadIdx.x;
    if (e < N_EDGES) {
        int s = edge_at(ei, e);
        int d = edge_at(ei, N_EDGES + e);
        int pos = g_rowstart[d] + atomicAdd(&g_fill[d], 1);
        g_colsrc[pos] = s;
        g_coledge[pos] = e;
    }
}

__global__ __launch_bounds__(256) void k_sortrows() {
    __shared__ int Es[8][MAX_DEG];
    __shared__ int Ss[8][MAX_DEG];
    int warp = (blockIdx.x * blockDim.x + threadIdx.x) >> 5;
    if (warp >= N_NODES) return;
    int lane = threadIdx.x & 31;
    int w = (threadIdx.x >> 5);
    int e0 = g_rowstart[warp], e1 = g_rowstart[warp + 1];
    int deg = e1 - e0;
    if (deg <= 1) return;
    if (deg > MAX_DEG) deg = MAX_DEG;
    for (int i = lane; i < deg; i += 32) {
        Es[w][i] = g_coledge[e0 + i];
        Ss[w][i] = g_colsrc[e0 + i];
    }
    __syncwarp();
    for (int i = lane; i < deg; i += 32) {
        int my_e = Es[w][i];
        int rank = 0;
        for (int j = 0; j < deg; j++) rank += (Es[w][j] < my_e);
        g_colsrc[e0 + rank] = Ss[w][i];
    }
}

// ---------------- GEMM (f32x2, double-buffered): C[65536x256] = A @ B --------
// Block tile 128x64, 256 threads, per-thread 8 rows (4 M-pairs) x 4 cols.
// Accumulation per output element identical to prior rounds:
// 16-deep IEEE-FMA k-tile chain, then add.rn into running sum.
template <int MODE>
__global__ __launch_bounds__(256) void k_gemm(
    const float* __restrict__ A0, const float* __restrict__ A1,
    const float* __restrict__ B0, const float* __restrict__ B1,
    float* __restrict__ C)
{
    __shared__ float As[2][16][130];
    __shared__ float Bs[2][16][64];
    int tid = threadIdx.x;
    int tx = tid & 15, ty = tid >> 4;
    int m0 = blockIdx.x * 128;
    int n0 = blockIdx.y * 64;

    // per-thread staging assignments
    int arow0 = tid >> 2;                 // A: 2 float4 per thread
    int aq0   = (tid & 3) * 4;
    int arow1 = (tid + 256) >> 2;
    int aq1   = aq0;                      // same (tid&3) pattern
    int brow  = tid >> 4;                 // B: 1 float4 per thread
    int bq    = (tid & 15) * 4;

    u64 acc[4][4];
    #pragma unroll
    for (int i = 0; i < 4; i++)
        #pragma unroll
        for (int j = 0; j < 4; j++) acc[i][j] = 0ull;

    float4 va0, va1, vb;
    // load tile 0 into regs
    {
        int col0 = aq0, col1 = aq1;
        if (MODE == 0) {
            va0 = (col0 < IN_DIM) ? *(const float4*)&A0[(m0 + arow0) * IN_DIM + col0]
                                  : *(const float4*)&A1[(m0 + arow0) * PE_DIM + (col0 - IN_DIM)];
            va1 = (col1 < IN_DIM) ? *(const float4*)&A0[(m0 + arow1) * IN_DIM + col1]
                                  : *(const float4*)&A1[(m0 + arow1) * PE_DIM + (col1 - IN_DIM)];
            vb  = *(const float4*)&B0[brow * 256 + n0 + bq];
        } else {
            va0 = *(const float4*)&A0[(m0 + arow0) * 256 + col0];
            va1 = *(const float4*)&A0[(m0 + arow1) * 256 + col1];
            int col = n0 + bq;
            vb = (col < 128) ? *(const float4*)&B0[brow * 128 + col]
                             : *(const float4*)&B1[brow * 128 + (col - 128)];
        }
    }

    #pragma unroll 1
    for (int t = 0; t < 16; t++) {
        int cur = t & 1;
        // store staged tile t
        As[cur][aq0 + 0][arow0] = va0.x; As[cur][aq0 + 1][arow0] = va0.y;
        As[cur][aq0 + 2][arow0] = va0.z; As[cur][aq0 + 3][arow0] = va0.w;
        As[cur][aq1 + 0][arow1] = va1.x; As[cur][aq1 + 1][arow1] = va1.y;
        As[cur][aq1 + 2][arow1] = va1.z; As[cur][aq1 + 3][arow1] = va1.w;
        *(float4*)&Bs[cur][brow][bq] = vb;
        __syncthreads();

        // prefetch tile t+1 while computing tile t
        if (t < 15) {
            int k0 = (t + 1) * 16;
            int col0 = k0 + aq0, col1 = k0 + aq1;
            if (MODE == 0) {
                va0 = (col0 < IN_DIM) ? *(const float4*)&A0[(m0 + arow0) * IN_DIM + col0]
                                      : *(const float4*)&A1[(m0 + arow0) * PE_DIM + (col0 - IN_DIM)];
                va1 = (col1 < IN_DIM) ? *(const float4*)&A0[(m0 + arow1) * IN_DIM + col1]
                                      : *(const float4*)&A1[(m0 + arow1) * PE_DIM + (col1 - IN_DIM)];
                vb  = *(const float4*)&B0[(k0 + brow) * 256 + n0 + bq];
            } else {
                va0 = *(const float4*)&A0[(m0 + arow0) * 256 + col0];
                va1 = *(const float4*)&A0[(m0 + arow1) * 256 + col1];
                int col = n0 + bq;
                vb = (col < 128) ? *(const float4*)&B0[(k0 + brow) * 128 + col]
                                 : *(const float4*)&B1[(k0 + brow) * 128 + (col - 128)];
            }
        }

        u64 accT[4][4];
        #pragma unroll
        for (int i = 0; i < 4; i++)
            #pragma unroll
            for (int j = 0; j < 4; j++) accT[i][j] = 0ull;

        #pragma unroll
        for (int k = 0; k < 16; k++) {
            u64 ap[4];
            #pragma unroll
            for (int i = 0; i < 4; i++)
                ap[i] = *(const u64*)&As[cur][k][ty * 8 + 2 * i];
            float4 bv = *(const float4*)&Bs[cur][k][tx * 4];
            u64 bp[4] = { pack2(bv.x, bv.x), pack2(bv.y, bv.y),
                          pack2(bv.z, bv.z), pack2(bv.w, bv.w) };
            #pragma unroll
            for (int i = 0; i < 4; i++)
                #pragma unroll
                for (int j = 0; j < 4; j++)
                    accT[i][j] = ffma2(ap[i], bp[j], accT[i][j]);
        }
        #pragma unroll
        for (int i = 0; i < 4; i++)
            #pragma unroll
            for (int j = 0; j < 4; j++)
                acc[i][j] = fadd2(acc[i][j], accT[i][j]);
        __syncthreads();
    }
    #pragma unroll
    for (int i = 0; i < 4; i++) {
        float lo[4], hi[4];
        #pragma unroll
        for (int j = 0; j < 4; j++) unpack2(acc[i][j], lo[j], hi[j]);
        int r0 = m0 + ty * 8 + 2 * i;
        *(float4*)&C[r0 * 256 + n0 + tx * 4]       = make_float4(lo[0], lo[1], lo[2], lo[3]);
        *(float4*)&C[(r0 + 1) * 256 + n0 + tx * 4] = make_float4(hi[0], hi[1], hi[2], hi[3]);
    }
}

// ---------------- normalized aggregation: 2 warps per node, 4-edge unroll ----
__global__ __launch_bounds__(256) void k_agg(
    const float* __restrict__ in, float* __restrict__ out,
    const float* __restrict__ bias0, const float* __restrict__ bias1, int relu)
{
    int gw = (blockIdx.x * blockDim.x + threadIdx.x) >> 5;
    if (gw >= N_NODES * 2) return;
    int lane = threadIdx.x & 31;
    int d = gw >> 1;
    int half = gw & 1;
    const float4* in4 = (const float4*)in + half * 32;
    float dd = g_dinv[d];

    float a0 = 0.f, a1 = 0.f, a2 = 0.f, a3 = 0.f;
    int e0 = g_rowstart[d], e1 = g_rowstart[d + 1];
    int e = e0;
    for (; e + 3 < e1; e += 4) {
        int s0 = g_colsrc[e], s1 = g_colsrc[e + 1];
        int s2 = g_colsrc[e + 2], s3 = g_colsrc[e + 3];
        float n0 = __fmul_rn(g_dinv[s0], dd);
        float n1 = __fmul_rn(g_dinv[s1], dd);
        float n2 = __fmul_rn(g_dinv[s2], dd);
        float n3 = __fmul_rn(g_dinv[s3], dd);
        float4 b0 = in4[s0 * 64 + lane];
        float4 b1 = in4[s1 * 64 + lane];
        float4 b2 = in4[s2 * 64 + lane];
        float4 b3 = in4[s3 * 64 + lane];
        a0 = __fadd_rn(a0, __fmul_rn(n0, b0.x));
        a1 = __fadd_rn(a1, __fmul_rn(n0, b0.y));
        a2 = __fadd_rn(a2, __fmul_rn(n0, b0.z));
        a3 = __fadd_rn(a3, __fmul_rn(n0, b0.w));
        a0 = __fadd_rn(a0, __fmul_rn(n1, b1.x));
        a1 = __fadd_rn(a1, __fmul_rn(n1, b1.y));
        a2 = __fadd_rn(a2, __fmul_rn(n1, b1.z));
        a3 = __fadd_rn(a3, __fmul_rn(n1, b1.w));
        a0 = __fadd_rn(a0, __fmul_rn(n2, b2.x));
        a1 = __fadd_rn(a1, __fmul_rn(n2, b2.y));
        a2 = __fadd_rn(a2, __fmul_rn(n2, b2.z));
        a3 = __fadd_rn(a3, __fmul_rn(n2, b2.w));
        a0 = __fadd_rn(a0, __fmul_rn(n3, b3.x));
        a1 = __fadd_rn(a1, __fmul_rn(n3, b3.y));
        a2 = __fadd_rn(a2, __fmul_rn(n3, b3.z));
        a3 = __fadd_rn(a3, __fmul_rn(n3, b3.w));
    }
    for (; e < e1; e++) {
        int s0 = g_colsrc[e];
        float n0 = __fmul_rn(g_dinv[s0], dd);
        float4 b0 = in4[s0 * 64 + lane];
        a0 = __fadd_rn(a0, __fmul_rn(n0, b0.x));
        a1 = __fadd_rn(a1, __fmul_rn(n0, b0.y));
        a2 = __fadd_rn(a2, __fmul_rn(n0, b0.z));
        a3 = __fadd_rn(a3, __fmul_rn(n0, b0.w));
    }
    {   // self loop last, as in reference edge list
        float ns = __fmul_rn(dd, dd);
        float4 b = in4[d * 64 + lane];
        a0 = __fadd_rn(a0, __fmul_rn(ns, b.x));
        a1 = __fadd_rn(a1, __fmul_rn(ns, b.y));
        a2 = __fadd_rn(a2, __fmul_rn(ns, b.z));
        a3 = __fadd_rn(a3, __fmul_rn(ns, b.w));
    }
    const float* bias = half ? bias1 : bias0;
    int c = lane * 4;
    a0 = __fadd_rn(a0, bias[c + 0]);
    a1 = __fadd_rn(a1, bias[c + 1]);
    a2 = __fadd_rn(a2, bias[c + 2]);
    a3 = __fadd_rn(a3, bias[c + 3]);
    if (relu) {
        a0 = fmaxf(a0, 0.f); a1 = fmaxf(a1, 0.f);
        a2 = fmaxf(a2, 0.f); a3 = fmaxf(a3, 0.f);
    }
    ((float4*)out + half * 32)[d * 64 + lane] = make_float4(a0, a1, a2, a3);
}

// ---------------- z = mu + eps*expf(0.5*lv); score via double dot ------------
__global__ __launch_bounds__(256) void k_zscore(
    const float* __restrict__ eps, const float* __restrict__ w)
{
    int warp = (blockIdx.x * blockDim.x + threadIdx.x) >> 5;
    if (warp >= N_NODES) return;
    int lane = threadIdx.x & 31;
    int n = warp;
    const float4* muv4 = (const float4*)g_buf1;
    float4 mu = muv4[n * 64 + lane];
    float4 lv = muv4[n * 64 + 32 + lane];
    float4 ep = ((const float4*)eps)[n * 32 + lane];
    float4 wv = ((const float4*)w)[lane];
    float4 z;
    z.x = __fadd_rn(mu.x, __fmul_rn(ep.x, expf(__fmul_rn(0.5f, lv.x))));
    z.y = __fadd_rn(mu.y, __fmul_rn(ep.y, expf(__fmul_rn(0.5f, lv.y))));
    z.z = __fadd_rn(mu.z, __fmul_rn(ep.z, expf(__fmul_rn(0.5f, lv.z))));
    z.w = __fadd_rn(mu.w, __fmul_rn(ep.w, expf(__fmul_rn(0.5f, lv.w))));
    double dot = (double)z.x * wv.x + (double)z.y * wv.y
               + (double)z.z * wv.z + (double)z.w * wv.w;
    double wsq = (double)wv.x * wv.x + (double)wv.y * wv.y
               + (double)wv.z * wv.z + (double)wv.w * wv.w;
    #pragma unroll
    for (int o = 16; o > 0; o >>= 1) {
        dot += __shfl_xor_sync(0xffffffffu, dot, o);
        wsq += __shfl_xor_sync(0xffffffffu, wsq, o);
    }
    ((float4*)g_z)[n * 32 + lane] = z;
    if (lane == 0) g_score[n] = (float)tanh(dot / sqrt(wsq));
}

// ---------------- per-graph top-k: bitonic sort of 1024 ----------------------
__device__ __forceinline__ bool later_than(float sa, int ia, float sb, int ib) {
    return (sa < sb) || (sa == sb && ia > ib);
}

__global__ __launch_bounds__(512) void k_topk() {
    __shared__ float ss[1024];
    __shared__ int   si[1024];
    int g = blockIdx.x;
    int t = threadIdx.x;
    int base = g * N_PER;
    ss[t] = g_score[base + t];             si[t] = t;
    ss[t + 512] = g_score[base + t + 512]; si[t + 512] = t + 512;
    __syncthreads();
    for (int k = 2; k <= 1024; k <<= 1) {
        for (int j = k >> 1; j > 0; j >>= 1) {
            for (int i = t; i < 1024; i += 512) {
                int l = i ^ j;
                if (l > i) {
                    bool up = ((i & k) == 0);
                    if (later_than(ss[i], si[i], ss[l], si[l]) == up) {
                        float ts = ss[i]; ss[i] = ss[l]; ss[l] = ts;
                        int ti = si[i]; si[i] = si[l]; si[l] = ti;
                    }
                }
            }
            __syncthreads();
        }
    }
    g_perm[g * K_PER + t] = base + si[t];
}

// ---------------- gather epilogue --------------------------------------------
__global__ __launch_bounds__(256) void k_output(float* __restrict__ out) {
    const int OFF_MU = N_OUT * LATENT;
    const int OFF_LV = 2 * N_OUT * LATENT;
    const int OFF_B  = 3 * N_OUT * LATENT;
    const int OFF_P  = OFF_B + N_OUT;
    int warp = (blockIdx.x * blockDim.x + threadIdx.x) >> 5;
    if (warp >= N_OUT) return;
    int lane = threadIdx.x & 31;
    int node = g_perm[warp];
    float sc = g_score[node];
    float4 z = ((const float4*)g_z)[node * 32 + lane];
    z.x = __fmul_rn(z.x, sc); z.y = __fmul_rn(z.y, sc);
    z.z = __fmul_rn(z.z, sc); z.w = __fmul_rn(z.w, sc);
    ((float4*)out)[warp * 32 + lane] = z;
    const float4* muv4 = (const float4*)g_buf1;
    ((float4*)(out + OFF_MU))[warp * 32 + lane] = muv4[node * 64 + lane];
    ((float4*)(out + OFF_LV))[warp * 32 + lane] = muv4[node * 64 + 32 + lane];
    if (lane == 0) {
        out[OFF_B + warp] = (float)(node >> 10);
        out[OFF_P + warp] = (float)node;
    }
}

// ---------------- launch ------------------------------------------------------
extern "C" void kernel_launch(void* const* d_in, const int* in_sizes, int n_in,
                              void* d_out, int out_size)
{
    const float* x_raw = (const float*)d_in[0];
    const float* pe    = (const float*)d_in[1];
    const void*  ei    = d_in[2];
    const float* eps   = (const float*)d_in[4];
    const float* W1    = (const float*)d_in[5];
    const float* b1    = (const float*)d_in[6];
    const float* Wmu   = (const float*)d_in[7];
    const float* bmu   = (const float*)d_in[8];
    const float* Wlv   = (const float*)d_in[9];
    const float* blv   = (const float*)d_in[10];
    const float* wpool = (const float*)d_in[11];
    float* out = (float*)d_out;

    float* buf0; cudaGetSymbolAddress((void**)&buf0, g_buf0);
    float* buf1; cudaGetSymbolAddress((void**)&buf1, g_buf1);

    // side stream + events, created once (outside any capture)
    static cudaStream_t s2 = 0;
    static cudaEvent_t evFork = 0, evJoin = 0;
    static int init_done = 0;
    if (!init_done) {
        init_done = 1;
        if (cudaStreamCreateWithFlags(&s2, cudaStreamNonBlocking) != cudaSuccess) s2 = 0;
        if (s2) {
            if (cudaEventCreateWithFlags(&evFork, cudaEventDisableTiming) != cudaSuccess ||
                cudaEventCreateWithFlags(&evJoin, cudaEventDisableTiming) != cudaSuccess)
                s2 = 0;
        }
    }

    dim3 gg(N_NODES / 128, 256 / 64);

    if (s2) {
        // fork: CSR build chain on side stream, GEMM1 on main stream
        cudaEventRecord(evFork, 0);
        cudaStreamWaitEvent(s2, evFork, 0);
        k_detect<<<1, 32, 0, s2>>>(ei);
        k_zero<<<N_NODES / 256, 256, 0, s2>>>();
        k_hist<<<N_EDGES / 256, 256, 0, s2>>>(ei);
        k_dinv<<<N_NODES / 256, 256, 0, s2>>>();
        k_scan<<<1, 1024, 0, s2>>>();
        k_scatter<<<N_EDGES / 256, 256, 0, s2>>>(ei);
        k_sortrows<<<(N_NODES * 32) / 256, 256, 0, s2>>>();
        cudaEventRecord(evJoin, s2);

        k_gemm<0><<<gg, 256>>>(x_raw, pe, W1, nullptr, buf0);
        cudaStreamWaitEvent(0, evJoin, 0);
    } else {
        k_detect<<<1, 32>>>(ei);
        k_zero<<<N_NODES / 256, 256>>>();
        k_hist<<<N_EDGES / 256, 256>>>(ei);
        k_dinv<<<N_NODES / 256, 256>>>();
        k_scan<<<1, 1024>>>();
        k_scatter<<<N_EDGES / 256, 256>>>(ei);
        k_sortrows<<<(N_NODES * 32) / 256, 256>>>();
        k_gemm<0><<<gg, 256>>>(x_raw, pe, W1, nullptr, buf0);
    }

    k_agg<<<(N_NODES * 64) / 256, 256>>>(buf0, buf1, b1, b1 + 128, 1);
    k_gemm<1><<<gg, 256>>>(buf1, nullptr, Wmu, Wlv, buf0);
    k_agg<<<(N_NODES * 64) / 256, 256>>>(buf0, buf1, bmu, blv, 0);

    k_zscore<<<(N_NODES * 32) / 256, 256>>>(eps, wpool);
    k_topk<<<NUM_G, 512>>>();
    k_output<<<(N_OUT * 32) / 256, 256>>>(out);
}